// round 7
// baseline (speedup 1.0000x reference)
#include <cuda_runtime.h>
#include <cuda_bf16.h>
#include <math.h>
#include <stdint.h>

#define TT 512
#define BB 64
#define KIN 1024
#define HH 1024
#define GG 4096   // 4*H

// ------------------------------------------------------------------
// Scratch (device globals: allocation is forbidden in kernel_launch)
// ------------------------------------------------------------------
__device__ float         g_x4[(size_t)TT * BB * GG];     // 512 MB fp32: X@Wx^T + b
__device__ __nv_bfloat16 g_xh[(size_t)TT * BB * KIN];    // X hi split
__device__ __nv_bfloat16 g_xl[(size_t)TT * BB * KIN];    // X lo split
__device__ __nv_bfloat16 g_wxh[(size_t)GG * KIN];        // Wx hi
__device__ __nv_bfloat16 g_wxl[(size_t)GG * KIN];        // Wx lo
__device__ unsigned      g_cpk[2][BB * HH];              // packed (hi<<16)|lo cell state
__device__ unsigned      g_cflag[8];                     // per-chunk-group publish counters

// ------------------------------------------------------------------
// helpers
// ------------------------------------------------------------------
__device__ __forceinline__ unsigned pack_split(float v) {
    __nv_bfloat16 h = __float2bfloat16_rn(v);
    float r = v - __bfloat162float(h);
    __nv_bfloat16 l = __float2bfloat16_rn(r);
    return ((unsigned)__bfloat16_as_ushort(h) << 16) |
           (unsigned)__bfloat16_as_ushort(l);
}

__device__ __forceinline__ uint32_t sh_addr(const void* p) {
    return (uint32_t)__cvta_generic_to_shared(p);
}

__device__ __forceinline__ unsigned ld_acquire(const unsigned* p) {
    unsigned v;
    asm volatile("ld.acquire.gpu.global.u32 %0, [%1];" : "=r"(v) : "l"(p));
    return v;
}

__device__ __forceinline__ void wait_flag(const unsigned* p, unsigned thresh) {
    while (ld_acquire(p) < thresh) { }
}

#define LDSM_X4(r, addr)                                                     \
    asm volatile("ldmatrix.sync.aligned.m8n8.x4.shared.b16 {%0,%1,%2,%3}, [%4];" \
                 : "=r"((r)[0]), "=r"((r)[1]), "=r"((r)[2]), "=r"((r)[3])    \
                 : "r"(addr))

#define MMA_BF16(d, a, b0, b1)                                               \
    asm volatile("mma.sync.aligned.m16n8k16.row.col.f32.bf16.bf16.f32 "      \
                 "{%0,%1,%2,%3}, {%4,%5,%6,%7}, {%8,%9}, {%0,%1,%2,%3};"     \
                 : "+f"((d)[0]), "+f"((d)[1]), "+f"((d)[2]), "+f"((d)[3])    \
                 : "r"((a)[0]), "r"((a)[1]), "r"((a)[2]), "r"((a)[3]),       \
                   "r"(b0), "r"(b1))

// ------------------------------------------------------------------
// Init: flags + seed packed c buffer
// ------------------------------------------------------------------
__global__ void init_kernel(const float* __restrict__ c0) {
    int idx = blockIdx.x * blockDim.x + threadIdx.x;
    if (idx < 8) g_cflag[idx] = 0u;
    if (idx < BB * HH) g_cpk[0][idx] = pack_split(c0[idx]);
}

// ------------------------------------------------------------------
// Split kernels: fp32 -> (hi, lo) bf16
// ------------------------------------------------------------------
__device__ __forceinline__ void split4_store(const float4* src, uint2* dh,
                                             uint2* dl, int i) {
    float4 v = src[i];
    unsigned p0 = pack_split(v.x), p1 = pack_split(v.y);
    unsigned p2 = pack_split(v.z), p3 = pack_split(v.w);
    dh[i] = make_uint2(__byte_perm(p0, p1, 0x7632), __byte_perm(p2, p3, 0x7632));
    dl[i] = make_uint2(__byte_perm(p0, p1, 0x5410), __byte_perm(p2, p3, 0x5410));
}

__global__ void split_x_kernel(const float* __restrict__ X) {
    int i = blockIdx.x * blockDim.x + threadIdx.x;
    const int n4 = TT * BB * KIN / 4;
    if (i < n4)
        split4_store((const float4*)X, (uint2*)g_xh, (uint2*)g_xl, i);
}

__global__ void split_w_kernel(const float* __restrict__ W) {
    int i = blockIdx.x * blockDim.x + threadIdx.x;
    const int n4 = GG * KIN / 4;
    if (i < n4)
        split4_store((const float4*)W, (uint2*)g_wxh, (uint2*)g_wxl, i);
}

// ------------------------------------------------------------------
// X4 GEMM via tensor cores (bf16 split, 3 phase products)
// v3: double-buffered smem (1 sync/chunk) + fused B LDSM (X4, 2 nt/ld)
// ------------------------------------------------------------------
#define XTILE (128 * 72)                  // elements per smem matrix buffer
#define XBUF_BYTES (XTILE * 2)            // bytes per buffer

extern __shared__ char smem_raw[];

__global__ void __launch_bounds__(256) x4_mma_kernel(const float* __restrict__ bias) {
    __nv_bfloat16* SA = (__nv_bfloat16*)smem_raw;            // [2][128][72]
    __nv_bfloat16* SB = SA + 2 * XTILE;                      // [2][128][72]

    const int tid  = threadIdx.x;
    const int lane = tid & 31;
    const int wid  = tid >> 5;
    const int wm   = wid >> 1;
    const int wn   = wid & 1;
    const int m0   = blockIdx.y * 128;
    const int n0   = blockIdx.x * 128;

    float acc[2][8][4];
#pragma unroll
    for (int mi = 0; mi < 2; ++mi)
#pragma unroll
        for (int nt = 0; nt < 8; ++nt)
#pragma unroll
            for (int e = 0; e < 4; ++e) acc[mi][nt][e] = 0.f;

    const uint32_t a_base =
        sh_addr(&SA[(wm * 32 + (lane & 15)) * 72 + (lane >> 4) * 8]);
    // fused-B ldmatrix: matrices 0,1 -> nt even (k halves), 2,3 -> nt odd
    const uint32_t b_base =
        sh_addr(&SB[(wn * 64 + ((lane >> 4) << 3) + (lane & 7)) * 72 +
                    ((lane >> 3) & 1) * 8]);

    const int lrow = tid >> 3;     // 0..31  (loads strided by 32 rows)
    const int lseg = tid & 7;

    // ---- prologue: LDG chunk 0, STS to buffer 0
    uint4 av[4], bv[4];
#pragma unroll
    for (int j = 0; j < 4; ++j) {
        int row = lrow + 32 * j;
        av[j] = *(const uint4*)(g_xh  + (size_t)(m0 + row) * KIN + lseg * 8);
        bv[j] = *(const uint4*)(g_wxh + (size_t)(n0 + row) * KIN + lseg * 8);
    }
#pragma unroll
    for (int j = 0; j < 4; ++j) {
        int row = lrow + 32 * j;
        *(uint4*)&SA[row * 72 + lseg * 8] = av[j];
        *(uint4*)&SB[row * 72 + lseg * 8] = bv[j];
    }
    __syncthreads();

    for (int kc2 = 0; kc2 < 48; ++kc2) {
        const uint32_t boff = (uint32_t)((kc2 & 1) * XBUF_BYTES);

        // issue LDG for next chunk (latency hidden under MMA pass)
        if (kc2 < 47) {
            int nk = kc2 + 1;
            int p  = nk >> 4;
            int kb = (nk & 15) << 6;
            const __nv_bfloat16* Asrc = (p == 1) ? g_xl : g_xh;
            const __nv_bfloat16* Bsrc = (p == 2) ? g_wxl : g_wxh;
#pragma unroll
            for (int j = 0; j < 4; ++j) {
                int row = lrow + 32 * j;
                av[j] = *(const uint4*)(Asrc + (size_t)(m0 + row) * KIN + kb + lseg * 8);
                bv[j] = *(const uint4*)(Bsrc + (size_t)(n0 + row) * KIN + kb + lseg * 8);
            }
        }

#pragma unroll
        for (int ks = 0; ks < 4; ++ks) {
            uint32_t a[2][4];
            LDSM_X4(a[0], a_base + boff + (uint32_t)(ks * 16) * 2);
            LDSM_X4(a[1], a_base + boff + (uint32_t)(16 * 72 + ks * 16) * 2);
#pragma unroll
            for (int ntp = 0; ntp < 4; ++ntp) {
                uint32_t b4[4];
                LDSM_X4(b4, b_base + boff +
                            (uint32_t)(ntp * 16 * 72 + ks * 16) * 2);
#pragma unroll
                for (int mi = 0; mi < 2; ++mi) {
                    MMA_BF16(acc[mi][2 * ntp],     a[mi], b4[0], b4[1]);
                    MMA_BF16(acc[mi][2 * ntp + 1], a[mi], b4[2], b4[3]);
                }
            }
        }

        // STS next chunk into the other buffer
        if (kc2 < 47) {
            __nv_bfloat16* SAd = SA + ((kc2 + 1) & 1) * XTILE;
            __nv_bfloat16* SBd = SB + ((kc2 + 1) & 1) * XTILE;
#pragma unroll
            for (int j = 0; j < 4; ++j) {
                int row = lrow + 32 * j;
                *(uint4*)&SAd[row * 72 + lseg * 8] = av[j];
                *(uint4*)&SBd[row * 72 + lseg * 8] = bv[j];
            }
        }
        __syncthreads();
    }

    // epilogue: bias + store fp32
    const int r0  = m0 + wm * 32 + (lane >> 2);
    const int c0c = n0 + wn * 64 + (lane & 3) * 2;
#pragma unroll
    for (int nt = 0; nt < 8; ++nt) {
        float2 bv2 = *(const float2*)&bias[c0c + nt * 8];
#pragma unroll
        for (int mi = 0; mi < 2; ++mi) {
            float* o = g_x4 + (size_t)(r0 + mi * 16) * GG + c0c + nt * 8;
            float2 v0 = make_float2(acc[mi][nt][0] + bv2.x, acc[mi][nt][1] + bv2.y);
            float2 v1 = make_float2(acc[mi][nt][2] + bv2.x, acc[mi][nt][3] + bv2.y);
            *(float2*)o            = v0;
            *(float2*)(o + 8 * GG) = v1;
        }
    }
}

// ------------------------------------------------------------------
// Persistent recurrence kernel, v3:
// 128 CTAs x 256 threads. No global barrier: chunk-group dataflow
// flags with staggered chunk order. Double-buffered Kc=128 c-chunks.
// ------------------------------------------------------------------
#define KC 128
#define NCHUNK (HH / KC)          // 8

struct RSmem {
    __nv_bfloat16 whH[32][1032];     // 66048 B
    __nv_bfloat16 whL[32][1032];     // 66048 B
    __nv_bfloat16 cH[2][64][KC + 8]; // 34816 B (double-buffered chunk)
    __nv_bfloat16 cL[2][64][KC + 8]; // 34816 B
    float pre[64][36];               //  9216 B
    float hs[64][8];                 //  2048 B
    float cs[64][8];                 //  2048 B
};                                   // 215040 B

#define CBUF_BYTES (64 * (KC + 8) * 2)   // 17408 per buffer

__global__ void __launch_bounds__(256, 1) lstm_persistent(
    const float* __restrict__ h0, const float* __restrict__ c0,
    const int* __restrict__ mask, const float* __restrict__ Wh,
    float* __restrict__ out)
{
    RSmem& S = *reinterpret_cast<RSmem*>(smem_raw);
    const int tid   = threadIdx.x;
    const int lane  = tid & 31;
    const int w     = tid >> 5;      // warp 0..7
    const int wm    = w & 3;         // m-slice (16 batch rows)
    const int wn    = w >> 2;        // n-half  (16 of 32 cols)
    const int ci    = blockIdx.x;
    const int jbase = ci * 8;
    const int s0    = ci >> 4;       // own chunk group / staggered start

    // ---- load Wh slice, split to bf16 hi/lo (resident all steps)
    for (int i = 0; i < 128; ++i) {
        int e = i * 256 + tid;           // 32768 elements
        int n = e >> 10, k = e & 1023;
        int grow = (n >> 3) * HH + jbase + (n & 7);
        float v = Wh[(size_t)grow * HH + k];
        __nv_bfloat16 h = __float2bfloat16_rn(v);
        float r = v - __bfloat162float(h);
        S.whH[n][k] = h;
        S.whL[n][k] = __float2bfloat16_rn(r);
    }
    // ---- init h / own-c state
    for (int p = tid; p < 512; p += 256) {
        int b = p >> 3, jj = p & 7;
        S.hs[b][jj] = h0[b * HH + jbase + jj];
        S.cs[b][jj] = c0[b * HH + jbase + jj];
    }
    __syncthreads();

    const uint32_t aH_base =
        sh_addr(&S.cH[0][wm * 16 + (lane & 15)][(lane >> 4) * 8]);
    const uint32_t aL_base =
        sh_addr(&S.cL[0][wm * 16 + (lane & 15)][(lane >> 4) * 8]);
    const uint32_t bH_base =
        sh_addr(&S.whH[wn * 16 + (lane & 7)][(lane >> 3) * 8]);
    const uint32_t bL_base =
        sh_addr(&S.whL[wn * 16 + (lane & 7)][(lane >> 3) * 8]);

    // ---- prefetch x4 + mask for step 0
    float x4v[2][4];
    int   mv[2];
#pragma unroll
    for (int r = 0; r < 2; ++r) {
        int p = tid + 256 * r;
        int b = p >> 3, jj = p & 7;
        const float* xp = g_x4 + ((size_t)0 * BB + b) * GG + jbase + jj;
        x4v[r][0] = xp[0];
        x4v[r][1] = xp[HH];
        x4v[r][2] = xp[2 * HH];
        x4v[r][3] = xp[3 * HH];
        mv[r] = mask[0 * BB + b];
    }

    for (int t = 0; t < TT; ++t) {
        const unsigned thresh = 16u * (unsigned)t;   // flags needed this step
        const uint4* csrc = (const uint4*)(g_cpk[t & 1]);   // [64][256] uint4

        // prologue: LDG chunk s0 (flag verified at end of previous step)
        uint4 v[8];
#pragma unroll
        for (int j2 = 0; j2 < 8; ++j2)
            v[j2] = __ldcg(&csrc[(w + 8 * j2) * 256 + s0 * 32 + lane]);

        float acc[2][4];
#pragma unroll
        for (int nt = 0; nt < 2; ++nt)
#pragma unroll
            for (int e = 0; e < 4; ++e) acc[nt][e] = 0.f;

#pragma unroll
        for (int kci = 0; kci < NCHUNK; ++kci) {
            const int kc  = (s0 + kci) & 7;       // physical chunk
            const int buf = kci & 1;
            __syncthreads();   // buffer `buf` free (MMA of kci-2 done)

            // ---- unpack regs -> smem chunk buffer
#pragma unroll
            for (int j2 = 0; j2 < 8; ++j2) {
                int row = w + 8 * j2;
                unsigned h01 = __byte_perm(v[j2].x, v[j2].y, 0x7632);
                unsigned l01 = __byte_perm(v[j2].x, v[j2].y, 0x5410);
                unsigned h23 = __byte_perm(v[j2].z, v[j2].w, 0x7632);
                unsigned l23 = __byte_perm(v[j2].z, v[j2].w, 0x5410);
                *(uint2*)&S.cH[buf][row][lane * 4] = make_uint2(h01, h23);
                *(uint2*)&S.cL[buf][row][lane * 4] = make_uint2(l01, l23);
            }
            // ---- issue LDG for next chunk (flag verified last iteration)
            if (kci < NCHUNK - 1) {
                const int kn = (s0 + kci + 1) & 7;
#pragma unroll
                for (int j2 = 0; j2 < 8; ++j2)
                    v[j2] = __ldcg(&csrc[(w + 8 * j2) * 256 + kn * 32 + lane]);
            }
            __syncthreads();

            // ---- verify flag for chunk kci+2 (usually already set;
            //      overlaps with the MMA pass below for other warps)
            if (kci < NCHUNK - 2)
                wait_flag(&g_cflag[(s0 + kci + 2) & 7], thresh);

            // ---- tensor-core products over this chunk (all 8 warps)
            const uint32_t abuf = (uint32_t)(buf * CBUF_BYTES);
#pragma unroll
            for (int g = 0; g < KC / 32; ++g) {
                uint32_t ah0[4], ah1[4], al0[4], al1[4];
                LDSM_X4(ah0, aH_base + abuf + (uint32_t)(g * 32) * 2);
                LDSM_X4(ah1, aH_base + abuf + (uint32_t)(g * 32 + 16) * 2);
                LDSM_X4(al0, aL_base + abuf + (uint32_t)(g * 32) * 2);
                LDSM_X4(al1, aL_base + abuf + (uint32_t)(g * 32 + 16) * 2);
                const uint32_t koff = (uint32_t)((kc * KC + g * 32) * 2);
#pragma unroll
                for (int nt = 0; nt < 2; ++nt) {
                    uint32_t bh[4], bl[4];
                    LDSM_X4(bh, bH_base + (uint32_t)(nt * 8 * 1032) * 2 + koff);
                    LDSM_X4(bl, bL_base + (uint32_t)(nt * 8 * 1032) * 2 + koff);
                    MMA_BF16(acc[nt], ah0, bh[0], bh[1]);
                    MMA_BF16(acc[nt], ah1, bh[2], bh[3]);
                    MMA_BF16(acc[nt], al0, bh[0], bh[1]);
                    MMA_BF16(acc[nt], al1, bh[2], bh[3]);
                    MMA_BF16(acc[nt], ah0, bl[0], bl[1]);
                    MMA_BF16(acc[nt], ah1, bl[2], bl[3]);
                }
            }
        }

        // ---- stage pre-activations through smem
        {
            int prow = wm * 16 + (lane >> 2);
            int pcol = (lane & 3) * 2;
#pragma unroll
            for (int nt = 0; nt < 2; ++nt) {
                int cb = (wn * 2 + nt) * 8 + pcol;
                S.pre[prow][cb]         = acc[nt][0];
                S.pre[prow][cb + 1]     = acc[nt][1];
                S.pre[prow + 8][cb]     = acc[nt][2];
                S.pre[prow + 8][cb + 1] = acc[nt][3];
            }
        }
        __syncthreads();

        // ---- gates + state update + publish c
        unsigned* cdst = g_cpk[(t + 1) & 1];
        float hv[2];
#pragma unroll
        for (int r = 0; r < 2; ++r) {
            int p = tid + 256 * r;
            int b = p >> 3, jj = p & 7;
            int jcol = jbase + jj;

            float pi = S.pre[b][jj]      + x4v[r][0];
            float pf = S.pre[b][8 + jj]  + x4v[r][1];
            float po = S.pre[b][16 + jj] + x4v[r][2];
            float pg = S.pre[b][24 + jj] + x4v[r][3];

            float ig = 1.f / (1.f + __expf(-pi));
            float fg = 1.f / (1.f + __expf(-pf));
            float og = 1.f / (1.f + __expf(-po));
            float gg = tanhf(pg);

            float cold = S.cs[b][jj];
            float cnew = fg * cold + ig * gg;
            float hold = S.hs[b][jj];
            int   m    = mv[r];
            float hnew = m ? (og * tanhf(cnew)) : hold;
            float cpub = m ? cnew : cold;

            S.hs[b][jj] = hnew;
            S.cs[b][jj] = cpub;
            hv[r] = hnew;
            cdst[b * HH + jcol] = pack_split(cpub);
        }

        // ---- publish: fence + group-flag increment (release)
        __threadfence();
        __syncthreads();
        if (tid == 0) atomicAdd(&g_cflag[s0], 1u);

        // ---- work not on the c critical path: h outputs + next prefetch
#pragma unroll
        for (int r = 0; r < 2; ++r) {
            int p = tid + 256 * r;
            int b = p >> 3, jj = p & 7;
            out[((size_t)t * BB + b) * HH + jbase + jj] = hv[r];
        }
        if (t + 1 < TT) {
#pragma unroll
            for (int r = 0; r < 2; ++r) {
                int p = tid + 256 * r;
                int b = p >> 3, jj = p & 7;
                const float* xp =
                    g_x4 + ((size_t)(t + 1) * BB + b) * GG + jbase + jj;
                x4v[r][0] = xp[0];
                x4v[r][1] = xp[HH];
                x4v[r][2] = xp[2 * HH];
                x4v[r][3] = xp[3 * HH];
                mv[r] = mask[(t + 1) * BB + b];
            }
            // verify flags for next step's first two chunks
            const unsigned tn = 16u * (unsigned)(t + 1);
            wait_flag(&g_cflag[s0], tn);
            wait_flag(&g_cflag[(s0 + 1) & 7], tn);
        }
    }

    // ---- finals: h_last, c_last appended after hiddens
    const size_t hid_elems = (size_t)TT * BB * HH;
    for (int p = tid; p < 512; p += 256) {
        int b = p >> 3, jj = p & 7;
        out[hid_elems + b * HH + jbase + jj]           = S.hs[b][jj];
        out[hid_elems + BB * HH + b * HH + jbase + jj] = S.cs[b][jj];
    }
}

// ------------------------------------------------------------------
// Launch
// ------------------------------------------------------------------
extern "C" void kernel_launch(void* const* d_in, const int* in_sizes, int n_in,
                              void* d_out, int out_size) {
    const float* X    = (const float*)d_in[0];
    const float* h0   = (const float*)d_in[1];
    const float* c0   = (const float*)d_in[2];
    const int*   mask = (const int*)d_in[3];
    const float* Wx   = (const float*)d_in[4];
    const float* Wh   = (const float*)d_in[5];
    const float* bias = (const float*)d_in[6];
    float* out = (float*)d_out;

    const int x4_smem = 4 * XTILE * 2;   // 73728 B
    cudaFuncSetAttribute(x4_mma_kernel,
                         cudaFuncAttributeMaxDynamicSharedMemorySize, x4_smem);
    cudaFuncSetAttribute(lstm_persistent,
                         cudaFuncAttributeMaxDynamicSharedMemorySize,
                         (int)sizeof(RSmem));

    init_kernel<<<256, 256>>>(c0);

    split_x_kernel<<<(TT * BB * KIN / 4 + 255) / 256, 256>>>(X);
    split_w_kernel<<<(GG * KIN / 4 + 255) / 256, 256>>>(Wx);

    dim3 g(GG / 128, (TT * BB) / 128);   // (32, 256)
    x4_mma_kernel<<<g, 256, x4_smem>>>(bias);

    lstm_persistent<<<128, 256, sizeof(RSmem)>>>(h0, c0, mask, Wh, out);
}

// round 8
// speedup vs baseline: 1.1127x; 1.1127x over previous
#include <cuda_runtime.h>
#include <cuda_bf16.h>
#include <math.h>
#include <stdint.h>

#define TT 512
#define BB 64
#define KIN 1024
#define HH 1024
#define GG 4096   // 4*H

// ------------------------------------------------------------------
// Scratch (device globals: allocation is forbidden in kernel_launch)
// ------------------------------------------------------------------
__device__ float         g_x4[(size_t)TT * BB * GG];     // 512 MB fp32: X@Wx^T + b
__device__ __nv_bfloat16 g_xh[(size_t)TT * BB * KIN];    // X hi split
__device__ __nv_bfloat16 g_xl[(size_t)TT * BB * KIN];    // X lo split
__device__ __nv_bfloat16 g_wxh[(size_t)GG * KIN];        // Wx hi
__device__ __nv_bfloat16 g_wxl[(size_t)GG * KIN];        // Wx lo
__device__ unsigned      g_cpk[2][BB * HH];              // packed (hi<<16)|lo cell state
__device__ unsigned      g_bar;                          // grid barrier counter

// ------------------------------------------------------------------
// helpers
// ------------------------------------------------------------------
__device__ __forceinline__ unsigned pack_split(float v) {
    __nv_bfloat16 h = __float2bfloat16_rn(v);
    float r = v - __bfloat162float(h);
    __nv_bfloat16 l = __float2bfloat16_rn(r);
    return ((unsigned)__bfloat16_as_ushort(h) << 16) |
           (unsigned)__bfloat16_as_ushort(l);
}

__device__ __forceinline__ uint32_t sh_addr(const void* p) {
    return (uint32_t)__cvta_generic_to_shared(p);
}

#define LDSM_X4(r, addr)                                                     \
    asm volatile("ldmatrix.sync.aligned.m8n8.x4.shared.b16 {%0,%1,%2,%3}, [%4];" \
                 : "=r"((r)[0]), "=r"((r)[1]), "=r"((r)[2]), "=r"((r)[3])    \
                 : "r"(addr))

#define MMA_BF16(d, a, b0, b1)                                               \
    asm volatile("mma.sync.aligned.m16n8k16.row.col.f32.bf16.bf16.f32 "      \
                 "{%0,%1,%2,%3}, {%4,%5,%6,%7}, {%8,%9}, {%0,%1,%2,%3};"     \
                 : "+f"((d)[0]), "+f"((d)[1]), "+f"((d)[2]), "+f"((d)[3])    \
                 : "r"((a)[0]), "r"((a)[1]), "r"((a)[2]), "r"((a)[3]),       \
                   "r"(b0), "r"(b1))

// ------------------------------------------------------------------
// Init: barrier + seed packed c buffer
// ------------------------------------------------------------------
__global__ void init_kernel(const float* __restrict__ c0) {
    int idx = blockIdx.x * blockDim.x + threadIdx.x;
    if (idx == 0) g_bar = 0u;
    if (idx < BB * HH) g_cpk[0][idx] = pack_split(c0[idx]);
}

// ------------------------------------------------------------------
// Split kernels: fp32 -> (hi, lo) bf16
// ------------------------------------------------------------------
__device__ __forceinline__ void split4_store(const float4* src, uint2* dh,
                                             uint2* dl, int i) {
    float4 v = src[i];
    unsigned p0 = pack_split(v.x), p1 = pack_split(v.y);
    unsigned p2 = pack_split(v.z), p3 = pack_split(v.w);
    dh[i] = make_uint2(__byte_perm(p0, p1, 0x7632), __byte_perm(p2, p3, 0x7632));
    dl[i] = make_uint2(__byte_perm(p0, p1, 0x5410), __byte_perm(p2, p3, 0x5410));
}

__global__ void split_x_kernel(const float* __restrict__ X) {
    int i = blockIdx.x * blockDim.x + threadIdx.x;
    const int n4 = TT * BB * KIN / 4;
    if (i < n4)
        split4_store((const float4*)X, (uint2*)g_xh, (uint2*)g_xl, i);
}

__global__ void split_w_kernel(const float* __restrict__ W) {
    int i = blockIdx.x * blockDim.x + threadIdx.x;
    const int n4 = GG * KIN / 4;
    if (i < n4)
        split4_store((const float4*)W, (uint2*)g_wxh, (uint2*)g_wxl, i);
}

// ------------------------------------------------------------------
// X4 GEMM via tensor cores (bf16 split, 3 phase products)
// v3 (R6, proven): double-buffered smem + fused B LDSM (X4, 2 nt/ld)
// ------------------------------------------------------------------
#define XTILE (128 * 72)                  // elements per smem matrix buffer
#define XBUF_BYTES (XTILE * 2)            // bytes per buffer

extern __shared__ char smem_raw[];

__global__ void __launch_bounds__(256) x4_mma_kernel(const float* __restrict__ bias) {
    __nv_bfloat16* SA = (__nv_bfloat16*)smem_raw;            // [2][128][72]
    __nv_bfloat16* SB = SA + 2 * XTILE;                      // [2][128][72]

    const int tid  = threadIdx.x;
    const int lane = tid & 31;
    const int wid  = tid >> 5;
    const int wm   = wid >> 1;
    const int wn   = wid & 1;
    const int m0   = blockIdx.y * 128;
    const int n0   = blockIdx.x * 128;

    float acc[2][8][4];
#pragma unroll
    for (int mi = 0; mi < 2; ++mi)
#pragma unroll
        for (int nt = 0; nt < 8; ++nt)
#pragma unroll
            for (int e = 0; e < 4; ++e) acc[mi][nt][e] = 0.f;

    const uint32_t a_base =
        sh_addr(&SA[(wm * 32 + (lane & 15)) * 72 + (lane >> 4) * 8]);
    // fused-B ldmatrix: matrices 0,1 -> nt even (k halves), 2,3 -> nt odd
    const uint32_t b_base =
        sh_addr(&SB[(wn * 64 + ((lane >> 4) << 3) + (lane & 7)) * 72 +
                    ((lane >> 3) & 1) * 8]);

    const int lrow = tid >> 3;     // 0..31  (loads strided by 32 rows)
    const int lseg = tid & 7;

    // ---- prologue: LDG chunk 0, STS to buffer 0
    uint4 av[4], bv[4];
#pragma unroll
    for (int j = 0; j < 4; ++j) {
        int row = lrow + 32 * j;
        av[j] = *(const uint4*)(g_xh  + (size_t)(m0 + row) * KIN + lseg * 8);
        bv[j] = *(const uint4*)(g_wxh + (size_t)(n0 + row) * KIN + lseg * 8);
    }
#pragma unroll
    for (int j = 0; j < 4; ++j) {
        int row = lrow + 32 * j;
        *(uint4*)&SA[row * 72 + lseg * 8] = av[j];
        *(uint4*)&SB[row * 72 + lseg * 8] = bv[j];
    }
    __syncthreads();

    for (int kc2 = 0; kc2 < 48; ++kc2) {
        const uint32_t boff = (uint32_t)((kc2 & 1) * XBUF_BYTES);

        // issue LDG for next chunk (latency hidden under MMA pass)
        if (kc2 < 47) {
            int nk = kc2 + 1;
            int p  = nk >> 4;
            int kb = (nk & 15) << 6;
            const __nv_bfloat16* Asrc = (p == 1) ? g_xl : g_xh;
            const __nv_bfloat16* Bsrc = (p == 2) ? g_wxl : g_wxh;
#pragma unroll
            for (int j = 0; j < 4; ++j) {
                int row = lrow + 32 * j;
                av[j] = *(const uint4*)(Asrc + (size_t)(m0 + row) * KIN + kb + lseg * 8);
                bv[j] = *(const uint4*)(Bsrc + (size_t)(n0 + row) * KIN + kb + lseg * 8);
            }
        }

#pragma unroll
        for (int ks = 0; ks < 4; ++ks) {
            uint32_t a[2][4];
            LDSM_X4(a[0], a_base + boff + (uint32_t)(ks * 16) * 2);
            LDSM_X4(a[1], a_base + boff + (uint32_t)(16 * 72 + ks * 16) * 2);
#pragma unroll
            for (int ntp = 0; ntp < 4; ++ntp) {
                uint32_t b4[4];
                LDSM_X4(b4, b_base + boff +
                            (uint32_t)(ntp * 16 * 72 + ks * 16) * 2);
#pragma unroll
                for (int mi = 0; mi < 2; ++mi) {
                    MMA_BF16(acc[mi][2 * ntp],     a[mi], b4[0], b4[1]);
                    MMA_BF16(acc[mi][2 * ntp + 1], a[mi], b4[2], b4[3]);
                }
            }
        }

        // STS next chunk into the other buffer
        if (kc2 < 47) {
            __nv_bfloat16* SAd = SA + ((kc2 + 1) & 1) * XTILE;
            __nv_bfloat16* SBd = SB + ((kc2 + 1) & 1) * XTILE;
#pragma unroll
            for (int j = 0; j < 4; ++j) {
                int row = lrow + 32 * j;
                *(uint4*)&SAd[row * 72 + lseg * 8] = av[j];
                *(uint4*)&SBd[row * 72 + lseg * 8] = bv[j];
            }
        }
        __syncthreads();
    }

    // epilogue: bias + store fp32
    const int r0  = m0 + wm * 32 + (lane >> 2);
    const int c0c = n0 + wn * 64 + (lane & 3) * 2;
#pragma unroll
    for (int nt = 0; nt < 8; ++nt) {
        float2 bv2 = *(const float2*)&bias[c0c + nt * 8];
#pragma unroll
        for (int mi = 0; mi < 2; ++mi) {
            float* o = g_x4 + (size_t)(r0 + mi * 16) * GG + c0c + nt * 8;
            float2 v0 = make_float2(acc[mi][nt][0] + bv2.x, acc[mi][nt][1] + bv2.y);
            float2 v1 = make_float2(acc[mi][nt][2] + bv2.x, acc[mi][nt][3] + bv2.y);
            *(float2*)o            = v0;
            *(float2*)(o + 8 * GG) = v1;
        }
    }
}

// ------------------------------------------------------------------
// Persistent recurrence kernel (R5-proven version):
// 128 CTAs x 256 threads (8 warps: 4 m-slices x 2 n-halves).
// Double-buffered Kc=128 c-chunks; split-phase single-counter barrier.
// ------------------------------------------------------------------
#define KC 128
#define NCHUNK (HH / KC)          // 8

struct RSmem {
    __nv_bfloat16 whH[32][1032];     // 66048 B
    __nv_bfloat16 whL[32][1032];     // 66048 B
    __nv_bfloat16 cH[2][64][KC + 8]; // 34816 B (double-buffered chunk)
    __nv_bfloat16 cL[2][64][KC + 8]; // 34816 B
    float pre[64][36];               //  9216 B
    float hs[64][8];                 //  2048 B
    float cs[64][8];                 //  2048 B
};                                   // 215040 B

#define CBUF_BYTES (64 * (KC + 8) * 2)   // 17408 per buffer

__global__ void __launch_bounds__(256, 1) lstm_persistent(
    const float* __restrict__ h0, const float* __restrict__ c0,
    const int* __restrict__ mask, const float* __restrict__ Wh,
    float* __restrict__ out)
{
    RSmem& S = *reinterpret_cast<RSmem*>(smem_raw);
    const int tid   = threadIdx.x;
    const int lane  = tid & 31;
    const int w     = tid >> 5;      // warp 0..7
    const int wm    = w & 3;         // m-slice (16 batch rows)
    const int wn    = w >> 2;        // n-half  (16 of 32 cols)
    const int ci    = blockIdx.x;
    const int jbase = ci * 8;

    // ---- load Wh slice, split to bf16 hi/lo (resident all steps)
    for (int i = 0; i < 128; ++i) {
        int e = i * 256 + tid;           // 32768 elements
        int n = e >> 10, k = e & 1023;
        int grow = (n >> 3) * HH + jbase + (n & 7);
        float v = Wh[(size_t)grow * HH + k];
        __nv_bfloat16 h = __float2bfloat16_rn(v);
        float r = v - __bfloat162float(h);
        S.whH[n][k] = h;
        S.whL[n][k] = __float2bfloat16_rn(r);
    }
    // ---- init h / own-c state
    for (int p = tid; p < 512; p += 256) {
        int b = p >> 3, jj = p & 7;
        S.hs[b][jj] = h0[b * HH + jbase + jj];
        S.cs[b][jj] = c0[b * HH + jbase + jj];
    }
    __syncthreads();

    const uint32_t aH_base =
        sh_addr(&S.cH[0][wm * 16 + (lane & 15)][(lane >> 4) * 8]);
    const uint32_t aL_base =
        sh_addr(&S.cL[0][wm * 16 + (lane & 15)][(lane >> 4) * 8]);
    const uint32_t bH_base =
        sh_addr(&S.whH[wn * 16 + (lane & 7)][(lane >> 3) * 8]);
    const uint32_t bL_base =
        sh_addr(&S.whL[wn * 16 + (lane & 7)][(lane >> 3) * 8]);

    unsigned bar_target = 0;

    // ---- prefetch x4 + mask for step 0
    float x4v[2][4];
    int   mv[2];
#pragma unroll
    for (int r = 0; r < 2; ++r) {
        int p = tid + 256 * r;
        int b = p >> 3, jj = p & 7;
        const float* xp = g_x4 + ((size_t)0 * BB + b) * GG + jbase + jj;
        x4v[r][0] = xp[0];
        x4v[r][1] = xp[HH];
        x4v[r][2] = xp[2 * HH];
        x4v[r][3] = xp[3 * HH];
        mv[r] = mask[0 * BB + b];
    }

    for (int t = 0; t < TT; ++t) {
        const uint4* csrc = (const uint4*)(g_cpk[t & 1]);   // [64][256] uint4

        // per-thread fixed unpack coordinates: row = w + 8*j2, k4 = lane
        // prologue: LDG chunk 0
        uint4 v[8];
#pragma unroll
        for (int j2 = 0; j2 < 8; ++j2)
            v[j2] = __ldcg(&csrc[(w + 8 * j2) * 256 + lane]);

        float acc[2][4];
#pragma unroll
        for (int nt = 0; nt < 2; ++nt)
#pragma unroll
            for (int e = 0; e < 4; ++e) acc[nt][e] = 0.f;

#pragma unroll
        for (int kc = 0; kc < NCHUNK; ++kc) {
            const int buf = kc & 1;
            __syncthreads();   // buffer `buf` free (MMA of kc-2 done)

            // ---- unpack regs -> smem chunk buffer
#pragma unroll
            for (int j2 = 0; j2 < 8; ++j2) {
                int row = w + 8 * j2;
                unsigned h01 = __byte_perm(v[j2].x, v[j2].y, 0x7632);
                unsigned l01 = __byte_perm(v[j2].x, v[j2].y, 0x5410);
                unsigned h23 = __byte_perm(v[j2].z, v[j2].w, 0x7632);
                unsigned l23 = __byte_perm(v[j2].z, v[j2].w, 0x5410);
                *(uint2*)&S.cH[buf][row][lane * 4] = make_uint2(h01, h23);
                *(uint2*)&S.cL[buf][row][lane * 4] = make_uint2(l01, l23);
            }
            // ---- issue LDG for next chunk (overlaps with MMA below)
            if (kc < NCHUNK - 1) {
#pragma unroll
                for (int j2 = 0; j2 < 8; ++j2)
                    v[j2] = __ldcg(&csrc[(w + 8 * j2) * 256 + (kc + 1) * 32 + lane]);
            }
            __syncthreads();

            // ---- tensor-core products over this chunk (all 8 warps)
            const uint32_t abuf = (uint32_t)(buf * CBUF_BYTES);
#pragma unroll
            for (int g = 0; g < KC / 32; ++g) {
                uint32_t ah0[4], ah1[4], al0[4], al1[4];
                LDSM_X4(ah0, aH_base + abuf + (uint32_t)(g * 32) * 2);
                LDSM_X4(ah1, aH_base + abuf + (uint32_t)(g * 32 + 16) * 2);
                LDSM_X4(al0, aL_base + abuf + (uint32_t)(g * 32) * 2);
                LDSM_X4(al1, aL_base + abuf + (uint32_t)(g * 32 + 16) * 2);
                const uint32_t koff = (uint32_t)((kc * KC + g * 32) * 2);
#pragma unroll
                for (int nt = 0; nt < 2; ++nt) {
                    uint32_t bh[4], bl[4];
                    LDSM_X4(bh, bH_base + (uint32_t)(nt * 8 * 1032) * 2 + koff);
                    LDSM_X4(bl, bL_base + (uint32_t)(nt * 8 * 1032) * 2 + koff);
                    MMA_BF16(acc[nt], ah0, bh[0], bh[1]);
                    MMA_BF16(acc[nt], ah1, bh[2], bh[3]);
                    MMA_BF16(acc[nt], al0, bh[0], bh[1]);
                    MMA_BF16(acc[nt], al1, bh[2], bh[3]);
                    MMA_BF16(acc[nt], ah0, bl[0], bl[1]);
                    MMA_BF16(acc[nt], ah1, bl[2], bl[3]);
                }
            }
        }

        // ---- stage pre-activations through smem
        {
            int prow = wm * 16 + (lane >> 2);
            int pcol = (lane & 3) * 2;
#pragma unroll
            for (int nt = 0; nt < 2; ++nt) {
                int cb = (wn * 2 + nt) * 8 + pcol;
                S.pre[prow][cb]         = acc[nt][0];
                S.pre[prow][cb + 1]     = acc[nt][1];
                S.pre[prow + 8][cb]     = acc[nt][2];
                S.pre[prow + 8][cb + 1] = acc[nt][3];
            }
        }
        __syncthreads();

        // ---- gates + state update + publish c
        unsigned* cdst = g_cpk[(t + 1) & 1];
        float hv[2];
#pragma unroll
        for (int r = 0; r < 2; ++r) {
            int p = tid + 256 * r;
            int b = p >> 3, jj = p & 7;
            int jcol = jbase + jj;

            float pi = S.pre[b][jj]      + x4v[r][0];
            float pf = S.pre[b][8 + jj]  + x4v[r][1];
            float po = S.pre[b][16 + jj] + x4v[r][2];
            float pg = S.pre[b][24 + jj] + x4v[r][3];

            float ig = 1.f / (1.f + __expf(-pi));
            float fg = 1.f / (1.f + __expf(-pf));
            float og = 1.f / (1.f + __expf(-po));
            float gg = tanhf(pg);

            float cold = S.cs[b][jj];
            float cnew = fg * cold + ig * gg;
            float hold = S.hs[b][jj];
            int   m    = mv[r];
            float hnew = m ? (og * tanhf(cnew)) : hold;
            float cpub = m ? cnew : cold;

            S.hs[b][jj] = hnew;
            S.cs[b][jj] = cpub;
            hv[r] = hnew;
            cdst[b * HH + jcol] = pack_split(cpub);
        }

        // ---- split-phase grid barrier: arrive, hide work, then wait
        __threadfence();
        __syncthreads();
        bar_target += gridDim.x;
        if (tid == 0) atomicAdd(&g_bar, 1u);

        // hidden work: write h outputs + prefetch next step's x4/mask
#pragma unroll
        for (int r = 0; r < 2; ++r) {
            int p = tid + 256 * r;
            int b = p >> 3, jj = p & 7;
            out[((size_t)t * BB + b) * HH + jbase + jj] = hv[r];
        }
        if (t + 1 < TT) {
#pragma unroll
            for (int r = 0; r < 2; ++r) {
                int p = tid + 256 * r;
                int b = p >> 3, jj = p & 7;
                const float* xp =
                    g_x4 + ((size_t)(t + 1) * BB + b) * GG + jbase + jj;
                x4v[r][0] = xp[0];
                x4v[r][1] = xp[HH];
                x4v[r][2] = xp[2 * HH];
                x4v[r][3] = xp[3 * HH];
                mv[r] = mask[(t + 1) * BB + b];
            }
        }

        if (tid == 0) {
            volatile unsigned* p = &g_bar;
            while (*p < bar_target) { __nanosleep(32); }
        }
        __syncthreads();
    }

    // ---- finals: h_last, c_last appended after hiddens
    const size_t hid_elems = (size_t)TT * BB * HH;
    for (int p = tid; p < 512; p += 256) {
        int b = p >> 3, jj = p & 7;
        out[hid_elems + b * HH + jbase + jj]           = S.hs[b][jj];
        out[hid_elems + BB * HH + b * HH + jbase + jj] = S.cs[b][jj];
    }
}

// ------------------------------------------------------------------
// Launch
// ------------------------------------------------------------------
extern "C" void kernel_launch(void* const* d_in, const int* in_sizes, int n_in,
                              void* d_out, int out_size) {
    const float* X    = (const float*)d_in[0];
    const float* h0   = (const float*)d_in[1];
    const float* c0   = (const float*)d_in[2];
    const int*   mask = (const int*)d_in[3];
    const float* Wx   = (const float*)d_in[4];
    const float* Wh   = (const float*)d_in[5];
    const float* bias = (const float*)d_in[6];
    float* out = (float*)d_out;

    const int x4_smem = 4 * XTILE * 2;   // 73728 B
    cudaFuncSetAttribute(x4_mma_kernel,
                         cudaFuncAttributeMaxDynamicSharedMemorySize, x4_smem);
    cudaFuncSetAttribute(lstm_persistent,
                         cudaFuncAttributeMaxDynamicSharedMemorySize,
                         (int)sizeof(RSmem));

    init_kernel<<<256, 256>>>(c0);

    split_x_kernel<<<(TT * BB * KIN / 4 + 255) / 256, 256>>>(X);
    split_w_kernel<<<(GG * KIN / 4 + 255) / 256, 256>>>(Wx);

    dim3 g(GG / 128, (TT * BB) / 128);   // (32, 256)
    x4_mma_kernel<<<g, 256, x4_smem>>>(bias);

    lstm_persistent<<<128, 256, sizeof(RSmem)>>>(h0, c0, mask, Wh, out);
}

// round 15
// speedup vs baseline: 1.1546x; 1.0376x over previous
#include <cuda_runtime.h>
#include <cuda_bf16.h>
#include <math.h>
#include <stdint.h>

#define TT 512
#define BB 64
#define KIN 1024
#define HH 1024
#define GG 4096   // 4*H

// ------------------------------------------------------------------
// Scratch (device globals: allocation is forbidden in kernel_launch)
// ------------------------------------------------------------------
__device__ float         g_x4[(size_t)TT * BB * GG];     // 512 MB fp32: X@Wx^T + b
__device__ __nv_bfloat16 g_xh[(size_t)TT * BB * KIN];    // X hi split
__device__ __nv_bfloat16 g_xl[(size_t)TT * BB * KIN];    // X lo split
__device__ __nv_bfloat16 g_wxh[(size_t)GG * KIN];        // Wx hi
__device__ __nv_bfloat16 g_wxl[(size_t)GG * KIN];        // Wx lo
__device__ unsigned      g_cpk[2][BB * HH];              // packed (hi<<16)|lo cell state
__device__ unsigned      g_bar;                          // grid barrier counter

// ------------------------------------------------------------------
// helpers
// ------------------------------------------------------------------
__device__ __forceinline__ unsigned pack_split(float v) {
    __nv_bfloat16 h = __float2bfloat16_rn(v);
    float r = v - __bfloat162float(h);
    __nv_bfloat16 l = __float2bfloat16_rn(r);
    return ((unsigned)__bfloat16_as_ushort(h) << 16) |
           (unsigned)__bfloat16_as_ushort(l);
}

__device__ __forceinline__ uint32_t sh_addr(const void* p) {
    return (uint32_t)__cvta_generic_to_shared(p);
}

#define LDSM_X4(r, addr)                                                     \
    asm volatile("ldmatrix.sync.aligned.m8n8.x4.shared.b16 {%0,%1,%2,%3}, [%4];" \
                 : "=r"((r)[0]), "=r"((r)[1]), "=r"((r)[2]), "=r"((r)[3])    \
                 : "r"(addr))

#define MMA_BF16(d, a, b0, b1)                                               \
    asm volatile("mma.sync.aligned.m16n8k16.row.col.f32.bf16.bf16.f32 "      \
                 "{%0,%1,%2,%3}, {%4,%5,%6,%7}, {%8,%9}, {%0,%1,%2,%3};"     \
                 : "+f"((d)[0]), "+f"((d)[1]), "+f"((d)[2]), "+f"((d)[3])    \
                 : "r"((a)[0]), "r"((a)[1]), "r"((a)[2]), "r"((a)[3]),       \
                   "r"(b0), "r"(b1))

#define BAR_SYNC(id)                                                         \
    asm volatile("bar.sync %0, 256;" :: "r"(id) : "memory")
#define BAR_ARRIVE(id)                                                       \
    asm volatile("bar.arrive %0, 256;" :: "r"(id) : "memory")

// ------------------------------------------------------------------
// Init: barrier + seed packed c buffer
// ------------------------------------------------------------------
__global__ void init_kernel(const float* __restrict__ c0) {
    int idx = blockIdx.x * blockDim.x + threadIdx.x;
    if (idx == 0) g_bar = 0u;
    if (idx < BB * HH) g_cpk[0][idx] = pack_split(c0[idx]);
}

// ------------------------------------------------------------------
// Split kernels: fp32 -> (hi, lo) bf16
// ------------------------------------------------------------------
__device__ __forceinline__ void split4_store(const float4* src, uint2* dh,
                                             uint2* dl, int i) {
    float4 v = src[i];
    unsigned p0 = pack_split(v.x), p1 = pack_split(v.y);
    unsigned p2 = pack_split(v.z), p3 = pack_split(v.w);
    dh[i] = make_uint2(__byte_perm(p0, p1, 0x7632), __byte_perm(p2, p3, 0x7632));
    dl[i] = make_uint2(__byte_perm(p0, p1, 0x5410), __byte_perm(p2, p3, 0x5410));
}

__global__ void split_x_kernel(const float* __restrict__ X) {
    int i = blockIdx.x * blockDim.x + threadIdx.x;
    const int n4 = TT * BB * KIN / 4;
    if (i < n4)
        split4_store((const float4*)X, (uint2*)g_xh, (uint2*)g_xl, i);
}

__global__ void split_w_kernel(const float* __restrict__ W) {
    int i = blockIdx.x * blockDim.x + threadIdx.x;
    const int n4 = GG * KIN / 4;
    if (i < n4)
        split4_store((const float4*)W, (uint2*)g_wxh, (uint2*)g_wxl, i);
}

// ------------------------------------------------------------------
// X4 GEMM via tensor cores (R6-proven, unchanged)
// ------------------------------------------------------------------
#define XTILE (128 * 72)
#define XBUF_BYTES (XTILE * 2)

extern __shared__ char smem_raw[];

__global__ void __launch_bounds__(256) x4_mma_kernel(const float* __restrict__ bias) {
    __nv_bfloat16* SA = (__nv_bfloat16*)smem_raw;
    __nv_bfloat16* SB = SA + 2 * XTILE;

    const int tid  = threadIdx.x;
    const int lane = tid & 31;
    const int wid  = tid >> 5;
    const int wm   = wid >> 1;
    const int wn   = wid & 1;
    const int m0   = blockIdx.y * 128;
    const int n0   = blockIdx.x * 128;

    float acc[2][8][4];
#pragma unroll
    for (int mi = 0; mi < 2; ++mi)
#pragma unroll
        for (int nt = 0; nt < 8; ++nt)
#pragma unroll
            for (int e = 0; e < 4; ++e) acc[mi][nt][e] = 0.f;

    const uint32_t a_base =
        sh_addr(&SA[(wm * 32 + (lane & 15)) * 72 + (lane >> 4) * 8]);
    const uint32_t b_base =
        sh_addr(&SB[(wn * 64 + ((lane >> 4) << 3) + (lane & 7)) * 72 +
                    ((lane >> 3) & 1) * 8]);

    const int lrow = tid >> 3;
    const int lseg = tid & 7;

    uint4 av[4], bv[4];
#pragma unroll
    for (int j = 0; j < 4; ++j) {
        int row = lrow + 32 * j;
        av[j] = *(const uint4*)(g_xh  + (size_t)(m0 + row) * KIN + lseg * 8);
        bv[j] = *(const uint4*)(g_wxh + (size_t)(n0 + row) * KIN + lseg * 8);
    }
#pragma unroll
    for (int j = 0; j < 4; ++j) {
        int row = lrow + 32 * j;
        *(uint4*)&SA[row * 72 + lseg * 8] = av[j];
        *(uint4*)&SB[row * 72 + lseg * 8] = bv[j];
    }
    __syncthreads();

    for (int kc2 = 0; kc2 < 48; ++kc2) {
        const uint32_t boff = (uint32_t)((kc2 & 1) * XBUF_BYTES);

        if (kc2 < 47) {
            int nk = kc2 + 1;
            int p  = nk >> 4;
            int kb = (nk & 15) << 6;
            const __nv_bfloat16* Asrc = (p == 1) ? g_xl : g_xh;
            const __nv_bfloat16* Bsrc = (p == 2) ? g_wxl : g_wxh;
#pragma unroll
            for (int j = 0; j < 4; ++j) {
                int row = lrow + 32 * j;
                av[j] = *(const uint4*)(Asrc + (size_t)(m0 + row) * KIN + kb + lseg * 8);
                bv[j] = *(const uint4*)(Bsrc + (size_t)(n0 + row) * KIN + kb + lseg * 8);
            }
        }

#pragma unroll
        for (int ks = 0; ks < 4; ++ks) {
            uint32_t a[2][4];
            LDSM_X4(a[0], a_base + boff + (uint32_t)(ks * 16) * 2);
            LDSM_X4(a[1], a_base + boff + (uint32_t)(16 * 72 + ks * 16) * 2);
#pragma unroll
            for (int ntp = 0; ntp < 4; ++ntp) {
                uint32_t b4[4];
                LDSM_X4(b4, b_base + boff +
                            (uint32_t)(ntp * 16 * 72 + ks * 16) * 2);
#pragma unroll
                for (int mi = 0; mi < 2; ++mi) {
                    MMA_BF16(acc[mi][2 * ntp],     a[mi], b4[0], b4[1]);
                    MMA_BF16(acc[mi][2 * ntp + 1], a[mi], b4[2], b4[3]);
                }
            }
        }

        if (kc2 < 47) {
            __nv_bfloat16* SAd = SA + ((kc2 + 1) & 1) * XTILE;
            __nv_bfloat16* SBd = SB + ((kc2 + 1) & 1) * XTILE;
#pragma unroll
            for (int j = 0; j < 4; ++j) {
                int row = lrow + 32 * j;
                *(uint4*)&SAd[row * 72 + lseg * 8] = av[j];
                *(uint4*)&SBd[row * 72 + lseg * 8] = bv[j];
            }
        }
        __syncthreads();
    }

    const int r0  = m0 + wm * 32 + (lane >> 2);
    const int c0c = n0 + wn * 64 + (lane & 3) * 2;
#pragma unroll
    for (int nt = 0; nt < 8; ++nt) {
        float2 bv2 = *(const float2*)&bias[c0c + nt * 8];
#pragma unroll
        for (int mi = 0; mi < 2; ++mi) {
            float* o = g_x4 + (size_t)(r0 + mi * 16) * GG + c0c + nt * 8;
            float2 v0 = make_float2(acc[mi][nt][0] + bv2.x, acc[mi][nt][1] + bv2.y);
            float2 v1 = make_float2(acc[mi][nt][2] + bv2.x, acc[mi][nt][3] + bv2.y);
            *(float2*)o            = v0;
            *(float2*)(o + 8 * GG) = v1;
        }
    }
}

// ------------------------------------------------------------------
// Persistent recurrence kernel v4: warp-specialized.
// 128 CTAs x 256 threads.
//   Warps 0-3 (MMA):    m32 x n16 tiles, 12 MMA + 6 LDSM per k16.
//   Warps 4-7 (staging): LDG packed c -> PRMT -> STS (double buffer).
// Producer/consumer via named barriers:
//   filled[buf]:   id 1+buf  (staging arrive, MMA sync)
//   consumed[buf]: id 3+buf  (MMA arrive, staging sync)
// pre[] stride = 34 floats (EVEN -> float2 stores stay 8B-aligned).
// ------------------------------------------------------------------
#define KC 128
#define NCHUNK (HH / KC)     // 8

// smem byte offsets
#define OFF_WHH  0                      // bf16 [32][1032]  66048
#define OFF_WHL  66048                  // bf16 [32][1032]  66048
#define OFF_CH   132096                 // bf16 [2][64][136] 34816
#define OFF_CL   166912                 // bf16 [2][64][136] 34816
#define OFF_PRE  201728                 // float [64][34]    8704
#define OFF_HS   210432                 // float [64][8]     2048
#define OFF_CS   212480                 // float [64][8]     2048
#define RSMEM_TOTAL 214528

#define PRE_STRIDE 34
#define CBUF_BYTES (64 * 136 * 2)       // 17408 per buffer
#define WH_ROW_B   (1032 * 2)           // 2064
#define CH_ROW_B   (136 * 2)            // 272

__global__ void __launch_bounds__(256, 1) lstm_persistent(
    const float* __restrict__ h0, const float* __restrict__ c0,
    const int* __restrict__ mask, const float* __restrict__ Wh,
    float* __restrict__ out)
{
    const int tid   = threadIdx.x;
    const int lane  = tid & 31;
    const int w     = tid >> 5;      // warp 0..7
    const int ci    = blockIdx.x;
    const int jbase = ci * 8;

    char* sm = smem_raw;
    const uint32_t smem_base = sh_addr(sm);
    __nv_bfloat16* whH = (__nv_bfloat16*)(sm + OFF_WHH);
    __nv_bfloat16* whL = (__nv_bfloat16*)(sm + OFF_WHL);
    float* preS = (float*)(sm + OFF_PRE);     // [64][PRE_STRIDE]
    float* hsS  = (float*)(sm + OFF_HS);
    float* csS  = (float*)(sm + OFF_CS);

    // ---- load Wh slice, split to bf16 hi/lo (resident all steps)
    for (int i = 0; i < 128; ++i) {
        int e = i * 256 + tid;           // 32768 elements
        int n = e >> 10, k = e & 1023;
        int grow = (n >> 3) * HH + jbase + (n & 7);
        float v = Wh[(size_t)grow * HH + k];
        __nv_bfloat16 h = __float2bfloat16_rn(v);
        float r = v - __bfloat162float(h);
        whH[n * 1032 + k] = h;
        whL[n * 1032 + k] = __float2bfloat16_rn(r);
    }
    // ---- init h / own-c state
    for (int p = tid; p < 512; p += 256) {
        int b = p >> 3, jj = p & 7;
        hsS[b * 8 + jj] = h0[b * HH + jbase + jj];
        csS[b * 8 + jj] = c0[b * HH + jbase + jj];
    }
    __syncthreads();

    // ---- MMA-warp addressing (warps 0-3): wm = w>>1, wn = w&1
    const int wm = (w >> 1) & 1;
    const int wn = w & 1;
    const uint32_t aH_base = smem_base + OFF_CH +
        (uint32_t)((wm * 32 + (lane & 15)) * CH_ROW_B + (lane >> 4) * 16);
    const uint32_t aL_base = smem_base + OFF_CL +
        (uint32_t)((wm * 32 + (lane & 15)) * CH_ROW_B + (lane >> 4) * 16);
    const uint32_t bH_base = smem_base + OFF_WHH +
        (uint32_t)((wn * 16 + ((lane >> 4) << 3) + (lane & 7)) * WH_ROW_B +
                   ((lane >> 3) & 1) * 16);
    const uint32_t bL_base = bH_base + (OFF_WHL - OFF_WHH);

    // ---- staging-warp addressing (warps 4-7)
    const int tid2 = tid - 128;              // 0..127 for staging threads
    const int r0   = (tid2 >> 5) & 3;        // base row 0..3
    const int k4   = tid2 & 31;              // uint4 index within chunk row
    const uint32_t sts_base = (uint32_t)(r0 * CH_ROW_B + k4 * 8);

    unsigned bar_target = 0;

    // ---- prefetch x4 + mask for step 0
    float x4v[2][4];
    int   mv[2];
#pragma unroll
    for (int r = 0; r < 2; ++r) {
        int p = tid + 256 * r;
        int b = p >> 3, jj = p & 7;
        const float* xp = g_x4 + ((size_t)0 * BB + b) * GG + jbase + jj;
        x4v[r][0] = xp[0];
        x4v[r][1] = xp[HH];
        x4v[r][2] = xp[2 * HH];
        x4v[r][3] = xp[3 * HH];
        mv[r] = mask[0 * BB + b];
    }

    for (int t = 0; t < TT; ++t) {
        if (w < 4) {
            // ================= MMA role =================
            float acc[2][2][4];
#pragma unroll
            for (int mt = 0; mt < 2; ++mt)
#pragma unroll
                for (int nt = 0; nt < 2; ++nt)
#pragma unroll
                    for (int e = 0; e < 4; ++e) acc[mt][nt][e] = 0.f;

#pragma unroll 1
            for (int kc = 0; kc < NCHUNK; ++kc) {
                const int buf = kc & 1;
                BAR_SYNC(1 + buf);                      // wait filled
                const uint32_t ab = (uint32_t)(buf * CBUF_BYTES);
#pragma unroll
                for (int g = 0; g < 8; ++g) {
                    uint32_t ah0[4], ah1[4], al0[4], al1[4], bh[4], bl[4];
                    const uint32_t ka = ab + (uint32_t)(g * 32);
                    LDSM_X4(ah0, aH_base + ka);
                    LDSM_X4(ah1, aH_base + ka + 16 * CH_ROW_B);
                    LDSM_X4(al0, aL_base + ka);
                    LDSM_X4(al1, aL_base + ka + 16 * CH_ROW_B);
                    const uint32_t koff = (uint32_t)(kc * 256 + g * 32);
                    LDSM_X4(bh, bH_base + koff);
                    LDSM_X4(bl, bL_base + koff);

                    MMA_BF16(acc[0][0], ah0, bh[0], bh[1]);
                    MMA_BF16(acc[0][1], ah0, bh[2], bh[3]);
                    MMA_BF16(acc[1][0], ah1, bh[0], bh[1]);
                    MMA_BF16(acc[1][1], ah1, bh[2], bh[3]);
                    MMA_BF16(acc[0][0], al0, bh[0], bh[1]);
                    MMA_BF16(acc[0][1], al0, bh[2], bh[3]);
                    MMA_BF16(acc[1][0], al1, bh[0], bh[1]);
                    MMA_BF16(acc[1][1], al1, bh[2], bh[3]);
                    MMA_BF16(acc[0][0], ah0, bl[0], bl[1]);
                    MMA_BF16(acc[0][1], ah0, bl[2], bl[3]);
                    MMA_BF16(acc[1][0], ah1, bl[0], bl[1]);
                    MMA_BF16(acc[1][1], ah1, bl[2], bl[3]);
                }
                BAR_ARRIVE(3 + buf);                    // signal consumed
            }

            // ---- write pre-activations to smem (8B-aligned: stride even)
            {
                int rl = lane >> 2;
                int cb = wn * 16 + (lane & 3) * 2;
#pragma unroll
                for (int mt = 0; mt < 2; ++mt) {
                    int row = wm * 32 + mt * 16 + rl;
#pragma unroll
                    for (int nt = 0; nt < 2; ++nt) {
                        int col = cb + nt * 8;
                        *(float2*)&preS[row * PRE_STRIDE + col] =
                            make_float2(acc[mt][nt][0], acc[mt][nt][1]);
                        *(float2*)&preS[(row + 8) * PRE_STRIDE + col] =
                            make_float2(acc[mt][nt][2], acc[mt][nt][3]);
                    }
                }
            }
        } else {
            // ================= staging role =================
            const uint4* csrc = (const uint4*)(g_cpk[t & 1]);
#pragma unroll 1
            for (int kc = 0; kc < NCHUNK; ++kc) {
                const int buf = kc & 1;
                const uint4* cp = csrc + r0 * 256 + kc * 32 + k4;
                uint4 va[4], vb[4];
#pragma unroll
                for (int i = 0; i < 4; ++i) va[i] = __ldcg(cp + i * 1024);
#pragma unroll
                for (int i = 0; i < 4; ++i) vb[i] = __ldcg(cp + (4 + i) * 1024);

                if (!(t == 0 && kc < 2)) BAR_SYNC(3 + buf);   // wait consumed

                char* chH = sm + OFF_CH + buf * CBUF_BYTES;
                char* chL = sm + OFF_CL + buf * CBUF_BYTES;

#pragma unroll
                for (int i = 0; i < 4; ++i) {
                    uint32_t o = sts_base + (uint32_t)(i * 4 * CH_ROW_B);
                    uint4 pv = va[i];
                    *(uint2*)(chH + o) = make_uint2(__byte_perm(pv.x, pv.y, 0x7632),
                                                    __byte_perm(pv.z, pv.w, 0x7632));
                    *(uint2*)(chL + o) = make_uint2(__byte_perm(pv.x, pv.y, 0x5410),
                                                    __byte_perm(pv.z, pv.w, 0x5410));
                }
#pragma unroll
                for (int i = 0; i < 4; ++i) va[i] = __ldcg(cp + (8 + i) * 1024);
#pragma unroll
                for (int i = 0; i < 4; ++i) {
                    uint32_t o = sts_base + (uint32_t)((4 + i) * 4 * CH_ROW_B);
                    uint4 pv = vb[i];
                    *(uint2*)(chH + o) = make_uint2(__byte_perm(pv.x, pv.y, 0x7632),
                                                    __byte_perm(pv.z, pv.w, 0x7632));
                    *(uint2*)(chL + o) = make_uint2(__byte_perm(pv.x, pv.y, 0x5410),
                                                    __byte_perm(pv.z, pv.w, 0x5410));
                }
#pragma unroll
                for (int i = 0; i < 4; ++i) vb[i] = __ldcg(cp + (12 + i) * 1024);
#pragma unroll
                for (int i = 0; i < 4; ++i) {
                    uint32_t o = sts_base + (uint32_t)((8 + i) * 4 * CH_ROW_B);
                    uint4 pv = va[i];
                    *(uint2*)(chH + o) = make_uint2(__byte_perm(pv.x, pv.y, 0x7632),
                                                    __byte_perm(pv.z, pv.w, 0x7632));
                    *(uint2*)(chL + o) = make_uint2(__byte_perm(pv.x, pv.y, 0x5410),
                                                    __byte_perm(pv.z, pv.w, 0x5410));
                }
#pragma unroll
                for (int i = 0; i < 4; ++i) {
                    uint32_t o = sts_base + (uint32_t)((12 + i) * 4 * CH_ROW_B);
                    uint4 pv = vb[i];
                    *(uint2*)(chH + o) = make_uint2(__byte_perm(pv.x, pv.y, 0x7632),
                                                    __byte_perm(pv.z, pv.w, 0x7632));
                    *(uint2*)(chL + o) = make_uint2(__byte_perm(pv.x, pv.y, 0x5410),
                                                    __byte_perm(pv.z, pv.w, 0x5410));
                }

                __threadfence_block();
                BAR_ARRIVE(1 + buf);                    // signal filled
            }
        }

        __syncthreads();   // pre ready for everyone

        // ---- gates + state update + publish c (all 256 threads)
        unsigned* cdst = g_cpk[(t + 1) & 1];
        float hv[2];
#pragma unroll
        for (int r = 0; r < 2; ++r) {
            int p = tid + 256 * r;
            int b = p >> 3, jj = p & 7;
            int jcol = jbase + jj;

            float pi = preS[b * PRE_STRIDE + jj]      + x4v[r][0];
            float pf = preS[b * PRE_STRIDE + 8 + jj]  + x4v[r][1];
            float po = preS[b * PRE_STRIDE + 16 + jj] + x4v[r][2];
            float pg = preS[b * PRE_STRIDE + 24 + jj] + x4v[r][3];

            float ig = 1.f / (1.f + __expf(-pi));
            float fg = 1.f / (1.f + __expf(-pf));
            float og = 1.f / (1.f + __expf(-po));
            float gg = tanhf(pg);

            float cold = csS[b * 8 + jj];
            float cnew = fg * cold + ig * gg;
            float hold = hsS[b * 8 + jj];
            int   m    = mv[r];
            float hnew = m ? (og * tanhf(cnew)) : hold;
            float cpub = m ? cnew : cold;

            hsS[b * 8 + jj] = hnew;
            csS[b * 8 + jj] = cpub;
            hv[r] = hnew;
            cdst[b * HH + jcol] = pack_split(cpub);
        }

        // ---- split-phase grid barrier: arrive, hide work, then wait
        __threadfence();
        __syncthreads();
        bar_target += gridDim.x;
        if (tid == 0) atomicAdd(&g_bar, 1u);

        // hidden work: write h outputs + prefetch next step's x4/mask
#pragma unroll
        for (int r = 0; r < 2; ++r) {
            int p = tid + 256 * r;
            int b = p >> 3, jj = p & 7;
            out[((size_t)t * BB + b) * HH + jbase + jj] = hv[r];
        }
        if (t + 1 < TT) {
#pragma unroll
            for (int r = 0; r < 2; ++r) {
                int p = tid + 256 * r;
                int b = p >> 3, jj = p & 7;
                const float* xp =
                    g_x4 + ((size_t)(t + 1) * BB + b) * GG + jbase + jj;
                x4v[r][0] = xp[0];
                x4v[r][1] = xp[HH];
                x4v[r][2] = xp[2 * HH];
                x4v[r][3] = xp[3 * HH];
                mv[r] = mask[(t + 1) * BB + b];
            }
        }

        if (tid == 0) {
            volatile unsigned* p = &g_bar;
            while (*p < bar_target) { __nanosleep(32); }
        }
        __syncthreads();
    }

    // ---- finals: h_last, c_last appended after hiddens
    const size_t hid_elems = (size_t)TT * BB * HH;
    for (int p = tid; p < 512; p += 256) {
        int b = p >> 3, jj = p & 7;
        out[hid_elems + b * HH + jbase + jj]           = hsS[b * 8 + jj];
        out[hid_elems + BB * HH + b * HH + jbase + jj] = csS[b * 8 + jj];
    }
}

// ------------------------------------------------------------------
// Launch
// ------------------------------------------------------------------
extern "C" void kernel_launch(void* const* d_in, const int* in_sizes, int n_in,
                              void* d_out, int out_size) {
    const float* X    = (const float*)d_in[0];
    const float* h0   = (const float*)d_in[1];
    const float* c0   = (const float*)d_in[2];
    const int*   mask = (const int*)d_in[3];
    const float* Wx   = (const float*)d_in[4];
    const float* Wh   = (const float*)d_in[5];
    const float* bias = (const float*)d_in[6];
    float* out = (float*)d_out;

    const int x4_smem = 4 * XTILE * 2;   // 73728 B
    cudaFuncSetAttribute(x4_mma_kernel,
                         cudaFuncAttributeMaxDynamicSharedMemorySize, x4_smem);
    cudaFuncSetAttribute(lstm_persistent,
                         cudaFuncAttributeMaxDynamicSharedMemorySize,
                         RSMEM_TOTAL);

    init_kernel<<<256, 256>>>(c0);

    split_x_kernel<<<(TT * BB * KIN / 4 + 255) / 256, 256>>>(X);
    split_w_kernel<<<(GG * KIN / 4 + 255) / 256, 256>>>(Wx);

    dim3 g(GG / 128, (TT * BB) / 128);   // (32, 256)
    x4_mma_kernel<<<g, 256, x4_smem>>>(bias);

    lstm_persistent<<<128, 256, RSMEM_TOTAL>>>(h0, c0, mask, Wh, out);
}